// round 1
// baseline (speedup 1.0000x reference)
#include <cuda_runtime.h>
#include <cstdint>

#define Tt 512
#define Bb 64
#define Ee 512
#define Hh 1024
#define Oo 512
#define GRID_P 148

// ---------------- device scratch (static: no allocations allowed) ----------------
__device__ float g_xp[Tt * Bb * Hh];      // (t, b, h) input projections, 128 MB
__device__ float g_h0[2][Bb * Hh];        // layer-0 hidden ping-pong
__device__ float g_h1[2][Bb * Hh];        // layer-1 hidden ping-pong
__device__ unsigned int g_cnt[2 * Tt + 1];// per-phase work counters
__device__ unsigned int g_bar;            // global barrier arrival counter

// ---------------- packed f32x2 helpers (FFMA2: 2x fp32 throughput) ----------------
__device__ __forceinline__ void ffma2(unsigned long long& d, unsigned long long a, unsigned long long b) {
    asm("fma.rn.f32x2 %0, %1, %2, %0;" : "+l"(d) : "l"(a), "l"(b));
}
__device__ __forceinline__ unsigned long long pack2(float x, float y) {
    unsigned long long r; asm("mov.b64 %0, {%1, %2};" : "=l"(r) : "f"(x), "f"(y)); return r;
}
__device__ __forceinline__ float2 unpack2(unsigned long long v) {
    float2 f; asm("mov.b64 {%0, %1}, %2;" : "=f"(f.x), "=f"(f.y) : "l"(v)); return f;
}

// ---------------- init: reset counters, load initial hidden state ----------------
__global__ void init_kernel(const float* __restrict__ h0in) {
    int idx = blockIdx.x * blockDim.x + threadIdx.x;
    if (idx < 2 * Tt + 1) g_cnt[idx] = 0;
    if (idx == 2 * Tt + 1) g_bar = 0;
    for (int i = idx; i < Bb * Hh; i += gridDim.x * blockDim.x) {
        g_h0[0][i] = h0in[i];
        g_h1[0][i] = h0in[Bb * Hh + i];
    }
}

// ---------------- xp = embeddings @ W_ih0^T + b_ih0, stored as (t,b,h) ----------------
// M = T*B = 32768 (row m = t*64+b), N = 1024, K = 512. Tile 128x64, 256 threads, 8x4/thread.
__global__ __launch_bounds__(256) void xp_gemm(const float* __restrict__ emb,
                                               const float* __restrict__ W,
                                               const float* __restrict__ bias) {
    __shared__ __align__(16) float As[16 * 132];  // [k][m], padded
    __shared__ __align__(16) float Bs[16 * 68];   // [k][n], padded
    const int tid = threadIdx.x;
    const int tx = tid & 15;          // n-frag: 4 cols
    const int ty = tid >> 4;          // m-frag: 8 rows
    const int m0 = blockIdx.y * 128;
    const int n0 = blockIdx.x * 64;

    unsigned long long acc[4][4];
#pragma unroll
    for (int i = 0; i < 4; i++)
#pragma unroll
        for (int j = 0; j < 4; j++) acc[i][j] = 0ull;

    for (int k0 = 0; k0 < Ee; k0 += 16) {
        // stage A: 128 rows x 16 k (rows are (t,b)-interleaved into embeddings)
#pragma unroll
        for (int rep = 0; rep < 2; rep++) {
            int f = tid + rep * 256;
            int m_l = f >> 2, kk = (f & 3) * 4;
            int m = m0 + m_l;
            int b = m & 63, t = m >> 6;
            const float4 v = *(const float4*)(emb + ((size_t)b * Tt + t) * Ee + k0 + kk);
            As[(kk + 0) * 132 + m_l] = v.x;
            As[(kk + 1) * 132 + m_l] = v.y;
            As[(kk + 2) * 132 + m_l] = v.z;
            As[(kk + 3) * 132 + m_l] = v.w;
        }
        // stage B: 64 rows of W x 16 k
        {
            int n_l = tid >> 2, kk = (tid & 3) * 4;
            const float4 v = *(const float4*)(W + (size_t)(n0 + n_l) * Ee + k0 + kk);
            Bs[(kk + 0) * 68 + n_l] = v.x;
            Bs[(kk + 1) * 68 + n_l] = v.y;
            Bs[(kk + 2) * 68 + n_l] = v.z;
            Bs[(kk + 3) * 68 + n_l] = v.w;
        }
        __syncthreads();
#pragma unroll
        for (int k = 0; k < 16; k++) {
            ulonglong2 aA = *(const ulonglong2*)&As[k * 132 + ty * 8];
            ulonglong2 aB = *(const ulonglong2*)&As[k * 132 + ty * 8 + 4];
            float4 bv = *(const float4*)&Bs[k * 68 + tx * 4];
            unsigned long long bd0 = pack2(bv.x, bv.x);
            unsigned long long bd1 = pack2(bv.y, bv.y);
            unsigned long long bd2 = pack2(bv.z, bv.z);
            unsigned long long bd3 = pack2(bv.w, bv.w);
            ffma2(acc[0][0], aA.x, bd0); ffma2(acc[0][1], aA.x, bd1);
            ffma2(acc[0][2], aA.x, bd2); ffma2(acc[0][3], aA.x, bd3);
            ffma2(acc[1][0], aA.y, bd0); ffma2(acc[1][1], aA.y, bd1);
            ffma2(acc[1][2], aA.y, bd2); ffma2(acc[1][3], aA.y, bd3);
            ffma2(acc[2][0], aB.x, bd0); ffma2(acc[2][1], aB.x, bd1);
            ffma2(acc[2][2], aB.x, bd2); ffma2(acc[2][3], aB.x, bd3);
            ffma2(acc[3][0], aB.y, bd0); ffma2(acc[3][1], aB.y, bd1);
            ffma2(acc[3][2], aB.y, bd2); ffma2(acc[3][3], aB.y, bd3);
        }
        __syncthreads();
    }
    // epilogue: + bias, store to g_xp[(t,b),h] (row m is already t*64+b)
#pragma unroll
    for (int i2 = 0; i2 < 4; i2++) {
#pragma unroll
        for (int j = 0; j < 4; j++) {
            float2 v = unpack2(acc[i2][j]);
            int m = m0 + ty * 8 + i2 * 2;
            int n = n0 + tx * 4 + j;
            float bb = bias[n];
            g_xp[(size_t)m * Hh + n]       = v.x + bb;
            g_xp[(size_t)(m + 1) * Hh + n] = v.y + bb;
        }
    }
}

// ---------------- persistent recurrent kernel ----------------
// One 32(batch) x 16(col) tile per work unit, K=1024 dot. Each thread owns 2 outputs
// (rows bg, bg+16 of column c0+cc), accumulated as packed f32x2 over K.
__device__ __forceinline__ float2 tile_dot(const float* __restrict__ A,
                                           const float* __restrict__ Wr,
                                           int b0, int cc, int bg, int tid,
                                           float* As, float* Ws) {
    unsigned long long acc0 = 0ull, acc1 = 0ull;
    for (int k0 = 0; k0 < Hh; k0 += 64) {
        __syncthreads();  // protect smem reuse
        {
            int row = tid >> 4, k4 = tid & 15;
            *(float4*)&As[row * 68 + k4 * 4] =
                *(const float4*)(A + (size_t)(b0 + row) * Hh + k0 + k4 * 4);
            int f1 = tid + 256;
            int row1 = f1 >> 4, k41 = f1 & 15;
            *(float4*)&As[row1 * 68 + k41 * 4] =
                *(const float4*)(A + (size_t)(b0 + row1) * Hh + k0 + k41 * 4);
            *(float4*)&Ws[row * 68 + k4 * 4] =
                *(const float4*)(Wr + (size_t)row * Hh + k0 + k4 * 4);
        }
        __syncthreads();
#pragma unroll
        for (int k4 = 0; k4 < 16; k4++) {
            ulonglong2 w  = *(const ulonglong2*)&Ws[cc * 68 + k4 * 4];
            ulonglong2 a0 = *(const ulonglong2*)&As[bg * 68 + k4 * 4];
            ulonglong2 a1 = *(const ulonglong2*)&As[(bg + 16) * 68 + k4 * 4];
            ffma2(acc0, a0.x, w.x); ffma2(acc0, a0.y, w.y);
            ffma2(acc1, a1.x, w.x); ffma2(acc1, a1.y, w.y);
        }
    }
    float2 f0 = unpack2(acc0), f1 = unpack2(acc1);
    return make_float2(f0.x + f0.y, f1.x + f1.y);
}

__device__ __forceinline__ void grid_barrier(unsigned int target) {
    __syncthreads();
    if (threadIdx.x == 0) {
        __threadfence();              // release all prior writes
        atomicAdd(&g_bar, 1u);
        while (*(volatile unsigned int*)&g_bar < target) { __nanosleep(64); }
        __threadfence();              // acquire
    }
    __syncthreads();
}

__global__ __launch_bounds__(256, 1) void rnn_persist(
    const float* __restrict__ W_hh0, const float* __restrict__ b_hh0,
    const float* __restrict__ W_ih1, const float* __restrict__ b_ih1,
    const float* __restrict__ W_hh1, const float* __restrict__ b_hh1,
    const float* __restrict__ W_out, const float* __restrict__ b_out,
    float* __restrict__ out) {
    __shared__ __align__(16) float As[32 * 68];
    __shared__ __align__(16) float Ws[16 * 68];
    __shared__ int s_unit;
    const int tid = threadIdx.x;
    const int cc = tid >> 4;   // 0..15 column within tile
    const int bg = tid & 15;   // 0..15 batch within tile (owns bg and bg+16)

    int p = 0;
    unsigned int barGen = 0;

    for (int t = 0; t < Tt; t++) {
        // ---- Phase 1: h0n(t) [units 0..127]  +  out(t-1) [units 128..191] ----
        const int nU = (t == 0) ? 128 : 192;
        while (true) {
            __syncthreads();
            if (tid == 0) s_unit = (int)atomicAdd(&g_cnt[2 * t], 1u);
            __syncthreads();
            int u = s_unit;
            if (u >= nU) break;
            if (u < 128) {
                int b0 = (u & 1) * 32, c0 = (u >> 1) * 16;
                float2 v = tile_dot(g_h0[p], W_hh0 + (size_t)c0 * Hh, b0, cc, bg, tid, As, Ws);
                int gc = c0 + cc;
                float bb = b_hh0[gc];
                int bA = b0 + bg, bB = b0 + bg + 16;
                const float* xpt = g_xp + (size_t)t * Bb * Hh;
                g_h0[1 - p][(size_t)bA * Hh + gc] = tanhf(v.x + xpt[(size_t)bA * Hh + gc] + bb);
                g_h0[1 - p][(size_t)bB * Hh + gc] = tanhf(v.y + xpt[(size_t)bB * Hh + gc] + bb);
            } else {
                int uu = u - 128;
                int b0 = (uu & 1) * 32, c0 = (uu >> 1) * 16;
                float2 v = tile_dot(g_h1[p], W_out + (size_t)c0 * Hh, b0, cc, bg, tid, As, Ws);
                int gc = c0 + cc;
                float bb = b_out[gc];
                out[((size_t)(b0 + bg) * Tt + (t - 1)) * Oo + gc]      = v.x + bb;
                out[((size_t)(b0 + bg + 16) * Tt + (t - 1)) * Oo + gc] = v.y + bb;
            }
        }
        grid_barrier(++barGen * GRID_P);

        // ---- Phase 2: h1n(t) = tanh(h0n@W_ih1^T + h1@W_hh1^T + biases) ----
        while (true) {
            __syncthreads();
            if (tid == 0) s_unit = (int)atomicAdd(&g_cnt[2 * t + 1], 1u);
            __syncthreads();
            int u = s_unit;
            if (u >= 128) break;
            int b0 = (u & 1) * 32, c0 = (u >> 1) * 16;
            float2 v1 = tile_dot(g_h0[1 - p], W_ih1 + (size_t)c0 * Hh, b0, cc, bg, tid, As, Ws);
            float2 v2 = tile_dot(g_h1[p],     W_hh1 + (size_t)c0 * Hh, b0, cc, bg, tid, As, Ws);
            int gc = c0 + cc;
            float bb = b_ih1[gc] + b_hh1[gc];
            g_h1[1 - p][(size_t)(b0 + bg) * Hh + gc]      = tanhf(v1.x + v2.x + bb);
            g_h1[1 - p][(size_t)(b0 + bg + 16) * Hh + gc] = tanhf(v1.y + v2.y + bb);
        }
        grid_barrier(++barGen * GRID_P);
        p ^= 1;
    }

    // ---- tail: out(T-1) from final h1 ----
    while (true) {
        __syncthreads();
        if (tid == 0) s_unit = (int)atomicAdd(&g_cnt[2 * Tt], 1u);
        __syncthreads();
        int u = s_unit;
        if (u >= 64) break;
        int b0 = (u & 1) * 32, c0 = (u >> 1) * 16;
        float2 v = tile_dot(g_h1[p], W_out + (size_t)c0 * Hh, b0, cc, bg, tid, As, Ws);
        int gc = c0 + cc;
        float bb = b_out[gc];
        out[((size_t)(b0 + bg) * Tt + (Tt - 1)) * Oo + gc]      = v.x + bb;
        out[((size_t)(b0 + bg + 16) * Tt + (Tt - 1)) * Oo + gc] = v.y + bb;
    }
}

// ---------------- launch ----------------
extern "C" void kernel_launch(void* const* d_in, const int* in_sizes, int n_in,
                              void* d_out, int out_size) {
    const float* emb   = (const float*)d_in[0];
    const float* h0    = (const float*)d_in[1];
    const float* W_ih0 = (const float*)d_in[2];
    const float* b_ih0 = (const float*)d_in[3];
    const float* W_ih1 = (const float*)d_in[4];
    const float* b_ih1 = (const float*)d_in[5];
    const float* W_hh0 = (const float*)d_in[6];
    const float* b_hh0 = (const float*)d_in[7];
    const float* W_hh1 = (const float*)d_in[8];
    const float* b_hh1 = (const float*)d_in[9];
    const float* W_out = (const float*)d_in[10];
    const float* b_out = (const float*)d_in[11];
    float* out = (float*)d_out;

    init_kernel<<<128, 256>>>(h0);
    xp_gemm<<<dim3(Hh / 64, (Tt * Bb) / 128), 256>>>(emb, W_ih0, b_ih0);
    rnn_persist<<<GRID_P, 256>>>(W_hh0, b_hh0, W_ih1, b_ih1, W_hh1, b_hh1,
                                 W_out, b_out, out);
}

// round 2
// speedup vs baseline: 1.0043x; 1.0043x over previous
#include <cuda_runtime.h>
#include <cstdint>

#define Tt 512
#define Bb 64
#define Ee 512
#define Hh 1024
#define Oo 512
#define GRID_P 148

// ---------------- device scratch (static: no allocations allowed) ----------------
__device__ float g_xp[Tt * Bb * Hh];      // (t, b, h) input projections, 128 MB
__device__ float g_h0[2][Bb * Hh];        // layer-0 hidden ping-pong
__device__ float g_h1[2][Bb * Hh];        // layer-1 hidden ping-pong
__device__ unsigned int g_cnt[2 * Tt + 1];// per-phase work counters
__device__ unsigned int g_bar;            // global barrier arrival counter

// ---------------- packed f32x2 helpers (FFMA2: 2x fp32 throughput) ----------------
__device__ __forceinline__ void ffma2(unsigned long long& d, unsigned long long a, unsigned long long b) {
    asm("fma.rn.f32x2 %0, %1, %2, %0;" : "+l"(d) : "l"(a), "l"(b));
}
__device__ __forceinline__ unsigned long long pack2(float x, float y) {
    unsigned long long r; asm("mov.b64 %0, {%1, %2};" : "=l"(r) : "f"(x), "f"(y)); return r;
}
__device__ __forceinline__ float2 unpack2(unsigned long long v) {
    float2 f; asm("mov.b64 {%0, %1}, %2;" : "=f"(f.x), "=f"(f.y) : "l"(v)); return f;
}

// ---------------- init: reset counters, load initial hidden state ----------------
__global__ void init_kernel(const float* __restrict__ h0in) {
    int idx = blockIdx.x * blockDim.x + threadIdx.x;
    if (idx < 2 * Tt + 1) g_cnt[idx] = 0;
    if (idx == 2 * Tt + 1) g_bar = 0;
    for (int i = idx; i < Bb * Hh; i += gridDim.x * blockDim.x) {
        g_h0[0][i] = h0in[i];
        g_h1[0][i] = h0in[Bb * Hh + i];
    }
}

// ---------------- xp = embeddings @ W_ih0^T + b_ih0, stored as (t,b,h) ----------------
// M = T*B = 32768 (row m = t*64+b), N = 1024, K = 512. Tile 128x64, 256 threads, 8x4/thread.
__global__ __launch_bounds__(256) void xp_gemm(const float* __restrict__ emb,
                                               const float* __restrict__ W,
                                               const float* __restrict__ bias) {
    __shared__ __align__(16) float As[16 * 132];  // [k][m], padded
    __shared__ __align__(16) float Bs[16 * 68];   // [k][n], padded
    const int tid = threadIdx.x;
    const int tx = tid & 15;          // n-frag: 4 cols
    const int ty = tid >> 4;          // m-frag: 8 rows
    const int m0 = blockIdx.y * 128;
    const int n0 = blockIdx.x * 64;

    unsigned long long acc[4][4];
#pragma unroll
    for (int i = 0; i < 4; i++)
#pragma unroll
        for (int j = 0; j < 4; j++) acc[i][j] = 0ull;

    for (int k0 = 0; k0 < Ee; k0 += 16) {
        // stage A: 128 rows x 16 k (rows are (t,b)-interleaved into embeddings)
#pragma unroll
        for (int rep = 0; rep < 2; rep++) {
            int f = tid + rep * 256;
            int m_l = f >> 2, kk = (f & 3) * 4;
            int m = m0 + m_l;
            int b = m & 63, t = m >> 6;
            const float4 v = *(const float4*)(emb + ((size_t)b * Tt + t) * Ee + k0 + kk);
            As[(kk + 0) * 132 + m_l] = v.x;
            As[(kk + 1) * 132 + m_l] = v.y;
            As[(kk + 2) * 132 + m_l] = v.z;
            As[(kk + 3) * 132 + m_l] = v.w;
        }
        // stage B: 64 rows of W x 16 k
        {
            int n_l = tid >> 2, kk = (tid & 3) * 4;
            const float4 v = *(const float4*)(W + (size_t)(n0 + n_l) * Ee + k0 + kk);
            Bs[(kk + 0) * 68 + n_l] = v.x;
            Bs[(kk + 1) * 68 + n_l] = v.y;
            Bs[(kk + 2) * 68 + n_l] = v.z;
            Bs[(kk + 3) * 68 + n_l] = v.w;
        }
        __syncthreads();
#pragma unroll
        for (int k = 0; k < 16; k++) {
            ulonglong2 aA = *(const ulonglong2*)&As[k * 132 + ty * 8];
            ulonglong2 aB = *(const ulonglong2*)&As[k * 132 + ty * 8 + 4];
            float4 bv = *(const float4*)&Bs[k * 68 + tx * 4];
            unsigned long long bd0 = pack2(bv.x, bv.x);
            unsigned long long bd1 = pack2(bv.y, bv.y);
            unsigned long long bd2 = pack2(bv.z, bv.z);
            unsigned long long bd3 = pack2(bv.w, bv.w);
            ffma2(acc[0][0], aA.x, bd0); ffma2(acc[0][1], aA.x, bd1);
            ffma2(acc[0][2], aA.x, bd2); ffma2(acc[0][3], aA.x, bd3);
            ffma2(acc[1][0], aA.y, bd0); ffma2(acc[1][1], aA.y, bd1);
            ffma2(acc[1][2], aA.y, bd2); ffma2(acc[1][3], aA.y, bd3);
            ffma2(acc[2][0], aB.x, bd0); ffma2(acc[2][1], aB.x, bd1);
            ffma2(acc[2][2], aB.x, bd2); ffma2(acc[2][3], aB.x, bd3);
            ffma2(acc[3][0], aB.y, bd0); ffma2(acc[3][1], aB.y, bd1);
            ffma2(acc[3][2], aB.y, bd2); ffma2(acc[3][3], aB.y, bd3);
        }
        __syncthreads();
    }
    // epilogue: + bias, store to g_xp[(t,b),h] (row m is already t*64+b)
#pragma unroll
    for (int i2 = 0; i2 < 4; i2++) {
#pragma unroll
        for (int j = 0; j < 4; j++) {
            float2 v = unpack2(acc[i2][j]);
            int m = m0 + ty * 8 + i2 * 2;
            int n = n0 + tx * 4 + j;
            float bb = bias[n];
            g_xp[(size_t)m * Hh + n]       = v.x + bb;
            g_xp[(size_t)(m + 1) * Hh + n] = v.y + bb;
        }
    }
}

// ---------------- persistent recurrent kernel ----------------
// One 32(batch) x 16(col) tile per work unit, K=1024 dot. Each thread owns 2 outputs
// (rows bg, bg+16 of column c0+cc), accumulated as packed f32x2 over K.
__device__ __forceinline__ float2 tile_dot(const float* __restrict__ A,
                                           const float* __restrict__ Wr,
                                           int b0, int cc, int bg, int tid,
                                           float* As, float* Ws) {
    unsigned long long acc0 = 0ull, acc1 = 0ull;
    for (int k0 = 0; k0 < Hh; k0 += 64) {
        __syncthreads();  // protect smem reuse
        {
            int row = tid >> 4, k4 = tid & 15;
            *(float4*)&As[row * 68 + k4 * 4] =
                *(const float4*)(A + (size_t)(b0 + row) * Hh + k0 + k4 * 4);
            int f1 = tid + 256;
            int row1 = f1 >> 4, k41 = f1 & 15;
            *(float4*)&As[row1 * 68 + k41 * 4] =
                *(const float4*)(A + (size_t)(b0 + row1) * Hh + k0 + k41 * 4);
            *(float4*)&Ws[row * 68 + k4 * 4] =
                *(const float4*)(Wr + (size_t)row * Hh + k0 + k4 * 4);
        }
        __syncthreads();
#pragma unroll
        for (int k4 = 0; k4 < 16; k4++) {
            ulonglong2 w  = *(const ulonglong2*)&Ws[cc * 68 + k4 * 4];
            ulonglong2 a0 = *(const ulonglong2*)&As[bg * 68 + k4 * 4];
            ulonglong2 a1 = *(const ulonglong2*)&As[(bg + 16) * 68 + k4 * 4];
            ffma2(acc0, a0.x, w.x); ffma2(acc0, a0.y, w.y);
            ffma2(acc1, a1.x, w.x); ffma2(acc1, a1.y, w.y);
        }
    }
    float2 f0 = unpack2(acc0), f1 = unpack2(acc1);
    return make_float2(f0.x + f0.y, f1.x + f1.y);
}

__device__ __forceinline__ void grid_barrier(unsigned int target) {
    __syncthreads();
    if (threadIdx.x == 0) {
        __threadfence();              // release all prior writes
        atomicAdd(&g_bar, 1u);
        while (*(volatile unsigned int*)&g_bar < target) { __nanosleep(64); }
        __threadfence();              // acquire
    }
    __syncthreads();
}

__global__ __launch_bounds__(256, 1) void rnn_persist(
    const float* __restrict__ W_hh0, const float* __restrict__ b_hh0,
    const float* __restrict__ W_ih1, const float* __restrict__ b_ih1,
    const float* __restrict__ W_hh1, const float* __restrict__ b_hh1,
    const float* __restrict__ W_out, const float* __restrict__ b_out,
    float* __restrict__ out) {
    __shared__ __align__(16) float As[32 * 68];
    __shared__ __align__(16) float Ws[16 * 68];
    __shared__ int s_unit;
    const int tid = threadIdx.x;
    const int cc = tid >> 4;   // 0..15 column within tile
    const int bg = tid & 15;   // 0..15 batch within tile (owns bg and bg+16)

    int p = 0;
    unsigned int barGen = 0;

    for (int t = 0; t < Tt; t++) {
        // ---- Phase 1: h0n(t) [units 0..127]  +  out(t-1) [units 128..191] ----
        const int nU = (t == 0) ? 128 : 192;
        while (true) {
            __syncthreads();
            if (tid == 0) s_unit = (int)atomicAdd(&g_cnt[2 * t], 1u);
            __syncthreads();
            int u = s_unit;
            if (u >= nU) break;
            if (u < 128) {
                int b0 = (u & 1) * 32, c0 = (u >> 1) * 16;
                float2 v = tile_dot(g_h0[p], W_hh0 + (size_t)c0 * Hh, b0, cc, bg, tid, As, Ws);
                int gc = c0 + cc;
                float bb = b_hh0[gc];
                int bA = b0 + bg, bB = b0 + bg + 16;
                const float* xpt = g_xp + (size_t)t * Bb * Hh;
                g_h0[1 - p][(size_t)bA * Hh + gc] = tanhf(v.x + xpt[(size_t)bA * Hh + gc] + bb);
                g_h0[1 - p][(size_t)bB * Hh + gc] = tanhf(v.y + xpt[(size_t)bB * Hh + gc] + bb);
            } else {
                int uu = u - 128;
                int b0 = (uu & 1) * 32, c0 = (uu >> 1) * 16;
                float2 v = tile_dot(g_h1[p], W_out + (size_t)c0 * Hh, b0, cc, bg, tid, As, Ws);
                int gc = c0 + cc;
                float bb = b_out[gc];
                out[((size_t)(b0 + bg) * Tt + (t - 1)) * Oo + gc]      = v.x + bb;
                out[((size_t)(b0 + bg + 16) * Tt + (t - 1)) * Oo + gc] = v.y + bb;
            }
        }
        grid_barrier(++barGen * GRID_P);

        // ---- Phase 2: h1n(t) = tanh(h0n@W_ih1^T + h1@W_hh1^T + biases) ----
        while (true) {
            __syncthreads();
            if (tid == 0) s_unit = (int)atomicAdd(&g_cnt[2 * t + 1], 1u);
            __syncthreads();
            int u = s_unit;
            if (u >= 128) break;
            int b0 = (u & 1) * 32, c0 = (u >> 1) * 16;
            float2 v1 = tile_dot(g_h0[1 - p], W_ih1 + (size_t)c0 * Hh, b0, cc, bg, tid, As, Ws);
            float2 v2 = tile_dot(g_h1[p],     W_hh1 + (size_t)c0 * Hh, b0, cc, bg, tid, As, Ws);
            int gc = c0 + cc;
            float bb = b_ih1[gc] + b_hh1[gc];
            g_h1[1 - p][(size_t)(b0 + bg) * Hh + gc]      = tanhf(v1.x + v2.x + bb);
            g_h1[1 - p][(size_t)(b0 + bg + 16) * Hh + gc] = tanhf(v1.y + v2.y + bb);
        }
        grid_barrier(++barGen * GRID_P);
        p ^= 1;
    }

    // ---- tail: out(T-1) from final h1 ----
    while (true) {
        __syncthreads();
        if (tid == 0) s_unit = (int)atomicAdd(&g_cnt[2 * Tt], 1u);
        __syncthreads();
        int u = s_unit;
        if (u >= 64) break;
        int b0 = (u & 1) * 32, c0 = (u >> 1) * 16;
        float2 v = tile_dot(g_h1[p], W_out + (size_t)c0 * Hh, b0, cc, bg, tid, As, Ws);
        int gc = c0 + cc;
        float bb = b_out[gc];
        out[((size_t)(b0 + bg) * Tt + (Tt - 1)) * Oo + gc]      = v.x + bb;
        out[((size_t)(b0 + bg + 16) * Tt + (Tt - 1)) * Oo + gc] = v.y + bb;
    }
}

// ---------------- launch ----------------
extern "C" void kernel_launch(void* const* d_in, const int* in_sizes, int n_in,
                              void* d_out, int out_size) {
    const float* emb   = (const float*)d_in[0];
    const float* h0    = (const float*)d_in[1];
    const float* W_ih0 = (const float*)d_in[2];
    const float* b_ih0 = (const float*)d_in[3];
    const float* W_ih1 = (const float*)d_in[4];
    const float* b_ih1 = (const float*)d_in[5];
    const float* W_hh0 = (const float*)d_in[6];
    const float* b_hh0 = (const float*)d_in[7];
    const float* W_hh1 = (const float*)d_in[8];
    const float* b_hh1 = (const float*)d_in[9];
    const float* W_out = (const float*)d_in[10];
    const float* b_out = (const float*)d_in[11];
    float* out = (float*)d_out;

    init_kernel<<<128, 256>>>(h0);
    xp_gemm<<<dim3(Hh / 64, (Tt * Bb) / 128), 256>>>(emb, W_ih0, b_ih0);
    rnn_persist<<<GRID_P, 256>>>(W_hh0, b_hh0, W_ih1, b_ih1, W_hh1, b_hh1,
                                 W_out, b_out, out);
}